// round 8
// baseline (speedup 1.0000x reference)
#include <cuda_runtime.h>
#include <cstdint>

// Problem constants (fixed shapes)
#define Bb   4
#define Ss   4096
#define Dd   1024
#define DFFc 4096
#define KACT 1024
#define BK   (Bb * KACT)   // 4096 selected rows total

// ---------------- device scratch (module globals; no runtime alloc) ---------
__device__ float g_scores[Bb * Ss];            // 64 KB
__device__ int   g_idx[BK];                    // selected token index per row
__device__ float g_gates[BK];                  // sigmoid(score) per row
__device__ float g_h[BK * DFFc];               // hidden activations, 64 MB

// ---------------- helpers ----------------------------------------------------
__device__ __forceinline__ void ffma2(unsigned long long& d,
                                      unsigned long long a,
                                      unsigned long long b) {
    asm("fma.rn.f32x2 %0, %1, %2, %0;" : "+l"(d) : "l"(a), "l"(b));
}
__device__ __forceinline__ float2 upk(unsigned long long p) {
    float2 r;
    asm("mov.b64 {%0, %1}, %2;" : "=f"(r.x), "=f"(r.y) : "l"(p));
    return r;
}
__device__ __forceinline__ float gelu_f(float v) {
    // exact GELU: 0.5*x*(1+erf(x/sqrt(2)))  (matches jax approximate=False)
    return 0.5f * v * (1.0f + erff(v * 0.70710678118654752440f));
}

// ---------------- 1) zero the output -----------------------------------------
__global__ void zero_kernel(float4* __restrict__ out, int n4) {
    int i = blockIdx.x * blockDim.x + threadIdx.x;
    int stride = gridDim.x * blockDim.x;
    float4 z = make_float4(0.f, 0.f, 0.f, 0.f);
    for (; i < n4; i += stride) out[i] = z;
}

// ---------------- 2) router scores: one warp per token ------------------------
__global__ void router_kernel(const float* __restrict__ x,
                              const float* __restrict__ rw,
                              const float* __restrict__ rb) {
    int warp = (blockIdx.x * blockDim.x + threadIdx.x) >> 5;
    int lane = threadIdx.x & 31;
    if (warp >= Bb * Ss) return;
    const float4* xr = reinterpret_cast<const float4*>(x) + (size_t)warp * (Dd / 4);
    const float4* w4 = reinterpret_cast<const float4*>(rw);
    float acc = 0.f;
#pragma unroll
    for (int i = 0; i < Dd / 128; ++i) {
        float4 a = xr[lane + i * 32];
        float4 b = w4[lane + i * 32];
        acc += a.x * b.x + a.y * b.y + a.z * b.z + a.w * b.w;
    }
#pragma unroll
    for (int o = 16; o; o >>= 1) acc += __shfl_xor_sync(0xffffffffu, acc, o);
    if (lane == 0) g_scores[warp] = acc + rb[0];
}

// ---------------- 3) exact top-1024 per batch row (bitonic sort, descending) --
__global__ void topk_kernel() {
    __shared__ float v[Ss];
    __shared__ int   id[Ss];
    int b = blockIdx.x;
    int t = threadIdx.x;
    for (int i = t; i < Ss; i += 1024) { v[i] = g_scores[b * Ss + i]; id[i] = i; }
    for (int k = 2; k <= Ss; k <<= 1) {
        for (int j = k >> 1; j > 0; j >>= 1) {
            __syncthreads();
            for (int i = t; i < Ss; i += 1024) {
                int l = i ^ j;
                if (l > i) {
                    float vi = v[i], vl = v[l];
                    bool up = ((i & k) == 0);            // descending overall
                    if (up ? (vi < vl) : (vi > vl)) {
                        v[i] = vl; v[l] = vi;
                        int tmp = id[i]; id[i] = id[l]; id[l] = tmp;
                    }
                }
            }
        }
    }
    __syncthreads();
    // first KACT entries are the top-k (t in [0,1024))
    g_idx[b * KACT + t]   = id[t];
    g_gates[b * KACT + t] = 1.f / (1.f + expf(-v[t]));
}

// ---------------- 4/5) fused GEMMs -------------------------------------------
// 128x128 block tile, KT=16, 256 threads, 8x8 per thread via packed f32x2 FFMA.
// A values stored DUPLICATED as float2 {v,v} in smem: inner loop is pure
// 128-bit LDS + FFMA2 (full-rate fp32 on B300). Double-buffered smem:
// one __syncthreads per K-tile.
// EPI==0: C = gelu(gather(x) @ w1 + b1) -> g_h   (K=1024, N=4096; A rows are
//          gathered from x through g_idx — gather fused into the A prologue)
// EPI==1: rows of (g_h @ w2 + b2) * gate scattered into out  (K=4096, N=1024)
template <int EPI>
__global__ __launch_bounds__(256, 2)
void gemm_kernel(const float* __restrict__ xin,    // x; only used by EPI==0
                 const float* __restrict__ Bg,     // weight matrix [K, N]
                 const float* __restrict__ bias,   // [N]
                 float* __restrict__ outp) {       // only used by EPI==1
    constexpr int K = (EPI == 0) ? Dd : DFFc;
    constexpr int N = (EPI == 0) ? DFFc : Dd;

    __shared__ __align__(16) float2 As[2][16][128];   // duplicated pairs, 32 KB
    __shared__ __align__(16) float  Bs[2][16][128];   // 16 KB  (total 48 KB)

    int tid = threadIdx.x;
    int m0 = blockIdx.y * 128, n0 = blockIdx.x * 128;
    int tx = tid & 15, ty = tid >> 4;
    int tm = ty * 8;
    int cn0 = tx * 4, cn1 = 64 + tx * 4;

    int rowA = tid >> 2, colA = (tid & 3) * 4;     // second chunk at rowA+64
    int rowB = tid >> 5, colB = (tid & 31) * 4;    // second chunk at rowB+8

    // A row base addresses. For EPI==0 the gather is fused: logical A row r is
    // x[(batch(r)*Ss + g_idx[r]) * Dd]. Row index is fixed per thread for the
    // whole K loop, so this is a one-time lookup.
    const float* Aptr;
    const float* Aptr2;
    if (EPI == 0) {
        int r1 = m0 + rowA, r2 = r1 + 64;
        size_t base = (size_t)(r1 >> 10) * Ss * Dd;   // batch const per tile
        Aptr  = xin + base + (size_t)g_idx[r1] * Dd + colA;
        Aptr2 = xin + base + (size_t)g_idx[r2] * Dd + colA;
    } else {
        Aptr  = g_h + (size_t)(m0 + rowA) * K + colA;
        Aptr2 = Aptr + (size_t)64 * K;
    }
    const float* Bptr  = Bg + (size_t)rowB * N + n0 + colB;
    const float* Bptr2 = Bptr + (size_t)8 * N;

    unsigned long long acc[8][4];
#pragma unroll
    for (int i = 0; i < 8; ++i)
#pragma unroll
        for (int j = 0; j < 4; ++j) acc[i][j] = 0ull;

    // prefetch tile 0 and commit to buffer 0
    float4 ra0 = *(const float4*)Aptr;
    float4 ra1 = *(const float4*)Aptr2;
    float4 rb0 = *(const float4*)Bptr;
    float4 rb1 = *(const float4*)Bptr2;

    As[0][colA + 0][rowA]      = make_float2(ra0.x, ra0.x);
    As[0][colA + 1][rowA]      = make_float2(ra0.y, ra0.y);
    As[0][colA + 2][rowA]      = make_float2(ra0.z, ra0.z);
    As[0][colA + 3][rowA]      = make_float2(ra0.w, ra0.w);
    As[0][colA + 0][rowA + 64] = make_float2(ra1.x, ra1.x);
    As[0][colA + 1][rowA + 64] = make_float2(ra1.y, ra1.y);
    As[0][colA + 2][rowA + 64] = make_float2(ra1.z, ra1.z);
    As[0][colA + 3][rowA + 64] = make_float2(ra1.w, ra1.w);
    *(float4*)&Bs[0][rowB][colB]     = rb0;
    *(float4*)&Bs[0][rowB + 8][colB] = rb1;
    __syncthreads();

    const int NT = K / 16;
    for (int t = 0; t < NT; ++t) {
        const int cur = t & 1;

        // issue next tile's global loads up front (latency overlap w/ compute)
        if (t + 1 < NT) {
            Aptr += 16; Aptr2 += 16;
            Bptr += (size_t)16 * N; Bptr2 += (size_t)16 * N;
            ra0 = *(const float4*)Aptr;
            ra1 = *(const float4*)Aptr2;
            rb0 = *(const float4*)Bptr;
            rb1 = *(const float4*)Bptr2;
        }

#pragma unroll
        for (int kk = 0; kk < 16; ++kk) {
            const ulonglong2* arow =
                reinterpret_cast<const ulonglong2*>(&As[cur][kk][tm]);
            ulonglong2 a0 = arow[0];   // av[0], av[1]
            ulonglong2 a1 = arow[1];   // av[2], av[3]
            ulonglong2 a2 = arow[2];   // av[4], av[5]
            ulonglong2 a3 = arow[3];   // av[6], av[7]
            const ulonglong2 bb0 = *reinterpret_cast<const ulonglong2*>(&Bs[cur][kk][cn0]);
            const ulonglong2 bb1 = *reinterpret_cast<const ulonglong2*>(&Bs[cur][kk][cn1]);
            unsigned long long av[8] = {a0.x, a0.y, a1.x, a1.y,
                                        a2.x, a2.y, a3.x, a3.y};
#pragma unroll
            for (int i = 0; i < 8; ++i) {
                ffma2(acc[i][0], av[i], bb0.x);
                ffma2(acc[i][1], av[i], bb0.y);
                ffma2(acc[i][2], av[i], bb1.x);
                ffma2(acc[i][3], av[i], bb1.y);
            }
        }

        // commit prefetched tile to the other buffer (safe: last read of that
        // buffer finished before the barrier at the end of iteration t-1)
        if (t + 1 < NT) {
            const int nxt = cur ^ 1;
            As[nxt][colA + 0][rowA]      = make_float2(ra0.x, ra0.x);
            As[nxt][colA + 1][rowA]      = make_float2(ra0.y, ra0.y);
            As[nxt][colA + 2][rowA]      = make_float2(ra0.z, ra0.z);
            As[nxt][colA + 3][rowA]      = make_float2(ra0.w, ra0.w);
            As[nxt][colA + 0][rowA + 64] = make_float2(ra1.x, ra1.x);
            As[nxt][colA + 1][rowA + 64] = make_float2(ra1.y, ra1.y);
            As[nxt][colA + 2][rowA + 64] = make_float2(ra1.z, ra1.z);
            As[nxt][colA + 3][rowA + 64] = make_float2(ra1.w, ra1.w);
            *(float4*)&Bs[nxt][rowB][colB]     = rb0;
            *(float4*)&Bs[nxt][rowB + 8][colB] = rb1;
        }
        __syncthreads();
    }

    // ------------- epilogue -------------
    float4 bv0 = *(const float4*)&bias[n0 + cn0];
    float4 bv1 = *(const float4*)&bias[n0 + cn1];
#pragma unroll
    for (int i = 0; i < 8; ++i) {
        int r = m0 + tm + i;
        float2 c0 = upk(acc[i][0]), c1 = upk(acc[i][1]);
        float2 c2 = upk(acc[i][2]), c3 = upk(acc[i][3]);
        float o0x = c0.x + bv0.x, o0y = c0.y + bv0.y;
        float o0z = c1.x + bv0.z, o0w = c1.y + bv0.w;
        float o1x = c2.x + bv1.x, o1y = c2.y + bv1.y;
        float o1z = c3.x + bv1.z, o1w = c3.y + bv1.w;
        if (EPI == 0) {
            float4 w0 = make_float4(gelu_f(o0x), gelu_f(o0y), gelu_f(o0z), gelu_f(o0w));
            float4 w1v = make_float4(gelu_f(o1x), gelu_f(o1y), gelu_f(o1z), gelu_f(o1w));
            *(float4*)&g_h[(size_t)r * DFFc + n0 + cn0] = w0;
            *(float4*)&g_h[(size_t)r * DFFc + n0 + cn1] = w1v;
        } else {
            int bb  = r >> 10;
            int tok = g_idx[r];
            float gt = g_gates[r];
            float* dst = outp + ((size_t)bb * Ss + tok) * Dd + n0;
            float4 w0 = make_float4(o0x * gt, o0y * gt, o0z * gt, o0w * gt);
            float4 w1v = make_float4(o1x * gt, o1y * gt, o1z * gt, o1w * gt);
            *(float4*)&dst[cn0] = w0;
            *(float4*)&dst[cn1] = w1v;
        }
    }
}

// ---------------- launch ------------------------------------------------------
extern "C" void kernel_launch(void* const* d_in, const int* in_sizes, int n_in,
                              void* d_out, int out_size) {
    const float* x  = (const float*)d_in[0];
    const float* rw = (const float*)d_in[1];
    const float* rb = (const float*)d_in[2];
    const float* w1 = (const float*)d_in[3];
    const float* b1 = (const float*)d_in[4];
    const float* w2 = (const float*)d_in[5];
    const float* b2 = (const float*)d_in[6];
    float* out = (float*)d_out;
    (void)in_sizes; (void)n_in; (void)out_size;

    zero_kernel<<<1184, 256>>>((float4*)out, (Bb * Ss * Dd) / 4);   // one full wave
    router_kernel<<<(Bb * Ss * 32) / 256, 256>>>(x, rw, rb);
    topk_kernel<<<Bb, 1024>>>();
    gemm_kernel<0><<<dim3(DFFc / 128, BK / 128), 256>>>(x, w1, b1, nullptr);
    gemm_kernel<1><<<dim3(Dd  / 128, BK / 128), 256>>>(x, w2, b2, out);
}

// round 15
// speedup vs baseline: 2.2499x; 2.2499x over previous
#include <cuda_runtime.h>
#include <cuda_bf16.h>
#include <cstdint>

// Problem constants
#define Bb   4
#define Ss   4096
#define Dd   1024
#define DFFc 4096
#define KACT 1024
#define BK   (Bb * KACT)

// ---------------- device scratch ---------------------------------------------
__device__ float g_scores[Bb * Ss];
__device__ int   g_idx[BK];
__device__ float g_gates[BK];
// bf16 split operand matrices (all K-major rows)
__device__ __align__(128) __nv_bfloat16 g_Ahi[BK * Dd],  g_Alo[BK * Dd];
__device__ __align__(128) __nv_bfloat16 g_W1hi[DFFc * Dd], g_W1lo[DFFc * Dd];
__device__ __align__(128) __nv_bfloat16 g_W2hi[Dd * DFFc], g_W2lo[Dd * DFFc];
__device__ __align__(128) __nv_bfloat16 g_Hhi[(size_t)BK * DFFc], g_Hlo[(size_t)BK * DFFc];

// ---------------- helpers -----------------------------------------------------
__device__ __forceinline__ uint32_t smem_to_u32(const void* p) {
    uint32_t a;
    asm("{ .reg .u64 t; cvta.to.shared.u64 t, %1; cvt.u32.u64 %0, t; }" : "=r"(a) : "l"(p));
    return a;
}
__device__ __forceinline__ void cp_async16(uint32_t saddr, const void* gptr) {
    asm volatile("cp.async.cg.shared.global [%0], [%1], 16;"
                 :: "r"(saddr), "l"(gptr) : "memory");
}
__device__ __forceinline__ void cp_commit() {
    asm volatile("cp.async.commit_group;" ::: "memory");
}
template <int N>
__device__ __forceinline__ void cp_wait() {
    asm volatile("cp.async.wait_group %0;" :: "n"(N) : "memory");
}
__device__ __forceinline__ void ldsm_x4(uint32_t& r0, uint32_t& r1, uint32_t& r2,
                                        uint32_t& r3, uint32_t addr) {
    asm volatile("ldmatrix.sync.aligned.m8n8.x4.shared.b16 {%0,%1,%2,%3}, [%4];"
                 : "=r"(r0), "=r"(r1), "=r"(r2), "=r"(r3) : "r"(addr));
}
__device__ __forceinline__ void mma_bf16(float* c, const uint32_t* a, const uint32_t* b) {
    asm volatile("mma.sync.aligned.m16n8k16.row.col.f32.bf16.bf16.f32 "
                 "{%0,%1,%2,%3}, {%4,%5,%6,%7}, {%8,%9}, {%0,%1,%2,%3};"
                 : "+f"(c[0]), "+f"(c[1]), "+f"(c[2]), "+f"(c[3])
                 : "r"(a[0]), "r"(a[1]), "r"(a[2]), "r"(a[3]), "r"(b[0]), "r"(b[1]));
}
__device__ __forceinline__ float gelu_f(float v) {
    return 0.5f * v * (1.0f + erff(v * 0.70710678118654752440f));
}
__device__ __forceinline__ void split_bf16(float a, __nv_bfloat16& h, __nv_bfloat16& l) {
    h = __float2bfloat16(a);
    l = __float2bfloat16(a - __bfloat162float(h));
}

// ---------------- small kernels ----------------------------------------------
__global__ void zero_kernel(float4* __restrict__ out, int n4) {
    int i = blockIdx.x * blockDim.x + threadIdx.x;
    int stride = gridDim.x * blockDim.x;
    float4 z = make_float4(0.f, 0.f, 0.f, 0.f);
    for (; i < n4; i += stride) out[i] = z;
}

__global__ void router_kernel(const float* __restrict__ x,
                              const float* __restrict__ rw,
                              const float* __restrict__ rb) {
    int warp = (blockIdx.x * blockDim.x + threadIdx.x) >> 5;
    int lane = threadIdx.x & 31;
    if (warp >= Bb * Ss) return;
    const float4* xr = reinterpret_cast<const float4*>(x) + (size_t)warp * (Dd / 4);
    const float4* w4 = reinterpret_cast<const float4*>(rw);
    float acc = 0.f;
#pragma unroll
    for (int i = 0; i < Dd / 128; ++i) {
        float4 a = xr[lane + i * 32];
        float4 b = w4[lane + i * 32];
        acc += a.x * b.x + a.y * b.y + a.z * b.z + a.w * b.w;
    }
#pragma unroll
    for (int o = 16; o; o >>= 1) acc += __shfl_xor_sync(0xffffffffu, acc, o);
    if (lane == 0) g_scores[warp] = acc + rb[0];
}

__global__ void topk_kernel() {
    __shared__ float v[Ss];
    __shared__ int   id[Ss];
    int b = blockIdx.x, t = threadIdx.x;
    for (int i = t; i < Ss; i += 1024) { v[i] = g_scores[b * Ss + i]; id[i] = i; }
    for (int k = 2; k <= Ss; k <<= 1)
        for (int j = k >> 1; j > 0; j >>= 1) {
            __syncthreads();
            for (int i = t; i < Ss; i += 1024) {
                int l = i ^ j;
                if (l > i) {
                    float vi = v[i], vl = v[l];
                    bool up = ((i & k) == 0);
                    if (up ? (vi < vl) : (vi > vl)) {
                        v[i] = vl; v[l] = vi;
                        int tmp = id[i]; id[i] = id[l]; id[l] = tmp;
                    }
                }
            }
        }
    __syncthreads();
    g_idx[b * KACT + t]   = id[t];
    g_gates[b * KACT + t] = 1.f / (1.f + expf(-v[t]));
}

__global__ void gatherconv_kernel(const float* __restrict__ x) {
    int r = blockIdx.x;
    int bb = r >> 10, tok = g_idx[r];
    const float4* src = reinterpret_cast<const float4*>(x + ((size_t)bb * Ss + tok) * Dd);
    float4 v = src[threadIdx.x];
    size_t o = (size_t)r * Dd + threadIdx.x * 4;
    __nv_bfloat16 h0, h1, h2, h3, l0, l1, l2, l3;
    split_bf16(v.x, h0, l0); split_bf16(v.y, h1, l1);
    split_bf16(v.z, h2, l2); split_bf16(v.w, h3, l3);
    *reinterpret_cast<__nv_bfloat162*>(&g_Ahi[o])     = __halves2bfloat162(h0, h1);
    *reinterpret_cast<__nv_bfloat162*>(&g_Ahi[o + 2]) = __halves2bfloat162(h2, h3);
    *reinterpret_cast<__nv_bfloat162*>(&g_Alo[o])     = __halves2bfloat162(l0, l1);
    *reinterpret_cast<__nv_bfloat162*>(&g_Alo[o + 2]) = __halves2bfloat162(l2, l3);
}

// transpose-and-split: W[R,C] fp32 -> T[C,R] bf16 hi/lo
template <int WSEL>
__global__ void transconv_kernel(const float* __restrict__ W) {
    constexpr int R = (WSEL == 1) ? Dd : DFFc;
    constexpr int C = (WSEL == 1) ? DFFc : Dd;
    __nv_bfloat16* Thi = (WSEL == 1) ? g_W1hi : g_W2hi;
    __nv_bfloat16* Tlo = (WSEL == 1) ? g_W1lo : g_W2lo;
    __shared__ float tile[32][33];
    int c0 = blockIdx.x * 32, r0 = blockIdx.y * 32;
    int tx = threadIdx.x, ty = threadIdx.y;
#pragma unroll
    for (int dy = 0; dy < 32; dy += 8)
        tile[ty + dy][tx] = W[(size_t)(r0 + ty + dy) * C + c0 + tx];
    __syncthreads();
#pragma unroll
    for (int dy = 0; dy < 32; dy += 8) {
        float a = tile[tx][ty + dy];
        __nv_bfloat16 h, l; split_bf16(a, h, l);
        size_t o = (size_t)(c0 + ty + dy) * R + r0 + tx;
        Thi[o] = h; Tlo[o] = l;
    }
}

// ---------------- mma.sync GEMM ----------------------------------------------
// CTA: 128x128, 8 warps (2 m x 4 n), warp: 64x32 = 4x4 m16n8k16 tiles.
// K chunk 32 bf16; smem tiles padded to 40 bf16/row (80B) -> conflict-free ldsm.
// D += Ahi*Bhi + Ahi*Blo + Alo*Bhi  (bf16 two-term split, fp32 accum).
static constexpr int KC = 32;
static constexpr int LDT = KC + 8;                       // 40 bf16 = 80 B
static constexpr int TILE_BYTES = 128 * LDT * 2;         // 10240
static constexpr int STAGE_BYTES = 4 * TILE_BYTES;       // 40960
static constexpr int GSMEM_TOTAL = 2 * STAGE_BYTES;      // 81920

template <int EPI>
__device__ __forceinline__ void issue_stage(const __nv_bfloat16* Ahi, const __nv_bfloat16* Alo,
                                            const __nv_bfloat16* Bhi, const __nv_bfloat16* Blo,
                                            int m0, int n0, int Kfull, int k0,
                                            uint32_t sb, int stage, int tid) {
    int row = tid >> 1;                 // 0..127
    int cb  = (tid & 1) * 2;            // chunk base 0 or 2
    const __nv_bfloat16* srcs[4] = { Ahi, Alo, Bhi, Blo };
    int bases[4] = { m0, m0, n0, n0 };
#pragma unroll
    for (int t = 0; t < 4; ++t) {
#pragma unroll
        for (int s = 0; s < 2; ++s) {
            int chunk = cb + s;         // 0..3, 8 bf16 each
            const void* g = srcs[t] + (size_t)(bases[t] + row) * Kfull + k0 + chunk * 8;
            uint32_t sa = sb + stage * STAGE_BYTES + t * TILE_BYTES +
                          (row * LDT + chunk * 8) * 2;
            cp_async16(sa, g);
        }
    }
}

template <int EPI>
__global__ __launch_bounds__(256, 2)
void gemm_mma_kernel(const float* __restrict__ bias, float* __restrict__ outp) {
    constexpr int Kfull = (EPI == 0) ? Dd : DFFc;
    constexpr int NIT   = Kfull / KC;
    const __nv_bfloat16* Ahi = (EPI == 0) ? g_Ahi  : g_Hhi;
    const __nv_bfloat16* Alo = (EPI == 0) ? g_Alo  : g_Hlo;
    const __nv_bfloat16* Bhi = (EPI == 0) ? g_W1hi : g_W2hi;
    const __nv_bfloat16* Blo = (EPI == 0) ? g_W1lo : g_W2lo;

    extern __shared__ char smem[];
    uint32_t sb = smem_to_u32(smem);
    int tid = threadIdx.x, wid = tid >> 5, lane = tid & 31;
    int n0 = blockIdx.x * 128, m0 = blockIdx.y * 128;
    int wm = (wid & 1) * 64, wn = (wid >> 1) * 32;

    float acc[4][4][4];
#pragma unroll
    for (int i = 0; i < 4; ++i)
#pragma unroll
        for (int j = 0; j < 4; ++j)
#pragma unroll
            for (int q = 0; q < 4; ++q) acc[i][j][q] = 0.f;

    // ldmatrix per-lane address components
    uint32_t aRow = (lane & 7) + ((lane >> 3) & 1) * 8;   // row within 16-row tile
    uint32_t aK   = (lane >> 4) * 8;                       // k offset 0/8
    uint32_t bN   = (lane & 7) + ((lane >> 4) << 3);       // n within 16
    uint32_t bK   = ((lane >> 3) & 1) << 3;                // k offset 0/8

    issue_stage<EPI>(Ahi, Alo, Bhi, Blo, m0, n0, Kfull, 0, sb, 0, tid);
    cp_commit();

    for (int it = 0; it < NIT; ++it) {
        int stg = it & 1;
        if (it + 1 < NIT) {
            issue_stage<EPI>(Ahi, Alo, Bhi, Blo, m0, n0, Kfull, (it + 1) * KC,
                             sb, (it + 1) & 1, tid);
            cp_commit();
            cp_wait<1>();
        } else {
            cp_wait<0>();
        }
        __syncthreads();

        uint32_t sA  = sb + stg * STAGE_BYTES;
        uint32_t sAl = sA + TILE_BYTES;
        uint32_t sB  = sA + 2 * TILE_BYTES;
        uint32_t sBl = sA + 3 * TILE_BYTES;
#pragma unroll
        for (int ks = 0; ks < 2; ++ks) {
            int k = ks * 16;
            uint32_t bhi[4][2], blo[4][2];
#pragma unroll
            for (int p = 0; p < 2; ++p) {
                uint32_t off = ((wn + p * 16 + bN) * LDT + k + bK) * 2;
                ldsm_x4(bhi[2 * p][0], bhi[2 * p][1], bhi[2 * p + 1][0], bhi[2 * p + 1][1],
                        sB + off);
                ldsm_x4(blo[2 * p][0], blo[2 * p][1], blo[2 * p + 1][0], blo[2 * p + 1][1],
                        sBl + off);
            }
#pragma unroll
            for (int mi = 0; mi < 4; ++mi) {
                uint32_t ah[4], al[4];
                uint32_t off = ((wm + mi * 16 + aRow) * LDT + k + aK) * 2;
                ldsm_x4(ah[0], ah[1], ah[2], ah[3], sA + off);
                ldsm_x4(al[0], al[1], al[2], al[3], sAl + off);
#pragma unroll
                for (int nj = 0; nj < 4; ++nj) {
                    mma_bf16(acc[mi][nj], ah, bhi[nj]);
                    mma_bf16(acc[mi][nj], ah, blo[nj]);
                    mma_bf16(acc[mi][nj], al, bhi[nj]);
                }
            }
        }
        __syncthreads();
    }

    // ------------- epilogue -------------
    int colq = 2 * (lane & 3);             // column pair base within 8-col tile
    int rbase = lane >> 2;                 // row 0..7 within 16-row tile
#pragma unroll
    for (int mi = 0; mi < 4; ++mi) {
#pragma unroll
        for (int h = 0; h < 2; ++h) {
            int m = m0 + wm + mi * 16 + rbase + h * 8;
            int bb = m >> 10;
            int tok  = (EPI == 1) ? g_idx[m]   : 0;
            float gt = (EPI == 1) ? g_gates[m] : 0.f;
#pragma unroll
            for (int nj = 0; nj < 4; ++nj) {
                int n = n0 + wn + nj * 8 + colq;
                float c0 = acc[mi][nj][2 * h]     + bias[n];
                float c1 = acc[mi][nj][2 * h + 1] + bias[n + 1];
                if (EPI == 0) {
                    float v0 = gelu_f(c0), v1 = gelu_f(c1);
                    __nv_bfloat16 h0, h1, l0, l1;
                    split_bf16(v0, h0, l0); split_bf16(v1, h1, l1);
                    size_t o = (size_t)m * DFFc + n;
                    *reinterpret_cast<__nv_bfloat162*>(&g_Hhi[o]) = __halves2bfloat162(h0, h1);
                    *reinterpret_cast<__nv_bfloat162*>(&g_Hlo[o]) = __halves2bfloat162(l0, l1);
                } else {
                    float2 w = make_float2(c0 * gt, c1 * gt);
                    *reinterpret_cast<float2*>(outp + ((size_t)bb * Ss + tok) * Dd + n) = w;
                }
            }
        }
    }
}

// ---------------- launch ------------------------------------------------------
extern "C" void kernel_launch(void* const* d_in, const int* in_sizes, int n_in,
                              void* d_out, int out_size) {
    const float* x  = (const float*)d_in[0];
    const float* rw = (const float*)d_in[1];
    const float* rb = (const float*)d_in[2];
    const float* w1 = (const float*)d_in[3];
    const float* b1 = (const float*)d_in[4];
    const float* w2 = (const float*)d_in[5];
    const float* b2 = (const float*)d_in[6];
    float* out = (float*)d_out;
    (void)in_sizes; (void)n_in; (void)out_size;

    cudaFuncSetAttribute(gemm_mma_kernel<0>,
                         cudaFuncAttributeMaxDynamicSharedMemorySize, GSMEM_TOTAL);
    cudaFuncSetAttribute(gemm_mma_kernel<1>,
                         cudaFuncAttributeMaxDynamicSharedMemorySize, GSMEM_TOTAL);

    zero_kernel<<<1184, 256>>>((float4*)out, (Bb * Ss * Dd) / 4);
    router_kernel<<<(Bb * Ss * 32) / 256, 256>>>(x, rw, rb);
    topk_kernel<<<Bb, 1024>>>();
    gatherconv_kernel<<<BK, 256>>>(x);
    transconv_kernel<1><<<dim3(DFFc / 32, Dd / 32), dim3(32, 8)>>>(w1);
    transconv_kernel<2><<<dim3(Dd / 32, DFFc / 32), dim3(32, 8)>>>(w2);
    gemm_mma_kernel<0><<<dim3(DFFc / 128, BK / 128), 256, GSMEM_TOTAL>>>(b1, nullptr);
    gemm_mma_kernel<1><<<dim3(Dd / 128,  BK / 128), 256, GSMEM_TOTAL>>>(b2, out);
}